// round 1
// baseline (speedup 1.0000x reference)
#include <cuda_runtime.h>
#include <math.h>

#define Dm 1024
#define Fm 4096
#define Em 8
#define Tm 4096
#define TK (Tm*2)

#define BM 128
#define BN 128
#define BK 16
#define PAD 4

// scratch (static device globals — no allocation)
__device__ int   g_count[Em];
__device__ int   g_entries[Em*Tm];      // entry = token*2 + slot
__device__ float g_topw[TK];
__device__ float g_H[(size_t)TK*Fm];    // 134 MB
__device__ float g_Y[(size_t)TK*Dm];    // 33.5 MB

__global__ void zero_counts_kernel() {
    if (threadIdx.x < Em) g_count[threadIdx.x] = 0;
}

// one warp per token: logits = x_t . Wr[e], softmax, top-2, scatter
__global__ void router_kernel(const float* __restrict__ x,
                              const float* __restrict__ Wr) {
    int w    = (blockIdx.x * blockDim.x + threadIdx.x) >> 5;
    int lane = threadIdx.x & 31;
    if (w >= Tm) return;
    const float* xr = x + (size_t)w * Dm;
    float acc[Em];
#pragma unroll
    for (int e = 0; e < Em; e++) acc[e] = 0.f;
    for (int j = lane; j < Dm; j += 32) {
        float xv = xr[j];
#pragma unroll
        for (int e = 0; e < Em; e++) acc[e] = fmaf(xv, Wr[e*Dm + j], acc[e]);
    }
#pragma unroll
    for (int e = 0; e < Em; e++) {
#pragma unroll
        for (int off = 16; off; off >>= 1)
            acc[e] += __shfl_xor_sync(0xffffffffu, acc[e], off);
    }
    if (lane == 0) {
        int e0 = 0; float v0 = acc[0];
#pragma unroll
        for (int e = 1; e < Em; e++) if (acc[e] > v0) { v0 = acc[e]; e0 = e; }
        int e1 = -1; float v1 = -1e30f;
#pragma unroll
        for (int e = 0; e < Em; e++) if (e != e0 && acc[e] > v1) { v1 = acc[e]; e1 = e; }
        // normalized top-2 softmax weights: w0 = e^{l0}/(e^{l0}+e^{l1})
        float b  = expf(v1 - v0);
        float w0 = 1.f / (1.f + b);
        float w1 = b  / (1.f + b);
        g_topw[w*2 + 0] = w0;
        g_topw[w*2 + 1] = w1;
        int p0 = atomicAdd(&g_count[e0], 1);
        g_entries[e0*Tm + p0] = w*2 + 0;
        int p1 = atomicAdd(&g_count[e1], 1);
        g_entries[e1*Tm + p1] = w*2 + 1;
    }
}

// H[entry] = gelu( x[token] @ W1[e]^T + b1[e] ), gathered rows per expert
__global__ __launch_bounds__(256, 2)
void gemm1_kernel(const float* __restrict__ x,
                  const float* __restrict__ W1,
                  const float* __restrict__ b1) {
    int e    = blockIdx.z;
    int cnt  = g_count[e];
    int row0 = blockIdx.y * BM;
    if (row0 >= cnt) return;
    int col0 = blockIdx.x * BN;

    __shared__ float As[BK][BM + PAD];
    __shared__ float Bs[BK][BN + PAD];
    __shared__ int   sEntry[BM];

    int tid = threadIdx.x;
    if (tid < BM) {
        int i = row0 + tid;
        sEntry[tid] = (i < cnt) ? g_entries[e*Tm + i] : -1;
    }
    __syncthreads();

    float acc[8][8];
#pragma unroll
    for (int i = 0; i < 8; i++)
#pragma unroll
        for (int j = 0; j < 8; j++) acc[i][j] = 0.f;

    const float* Wb = W1 + (size_t)e*Fm*Dm + (size_t)col0*Dm;
    int tx = tid & 15, ty = tid >> 4;

    for (int k0 = 0; k0 < Dm; k0 += BK) {
#pragma unroll
        for (int j = 0; j < 8; j++) {
            int idx = tid + j*256;
            int k = idx & (BK-1);
            int m = idx >> 4;
            int en = sEntry[m];
            int t  = (en >= 0) ? (en >> 1) : 0;
            As[k][m] = x[(size_t)t*Dm + k0 + k];
        }
#pragma unroll
        for (int j = 0; j < 8; j++) {
            int idx = tid + j*256;
            int k = idx & (BK-1);
            int n = idx >> 4;
            Bs[k][n] = Wb[(size_t)n*Dm + k0 + k];
        }
        __syncthreads();
#pragma unroll
        for (int k = 0; k < BK; k++) {
            float a[8], bfr[8];
            *(float4*)&a[0]   = *(const float4*)&As[k][ty*8];
            *(float4*)&a[4]   = *(const float4*)&As[k][ty*8 + 4];
            *(float4*)&bfr[0] = *(const float4*)&Bs[k][tx*8];
            *(float4*)&bfr[4] = *(const float4*)&Bs[k][tx*8 + 4];
#pragma unroll
            for (int i = 0; i < 8; i++)
#pragma unroll
                for (int j = 0; j < 8; j++)
                    acc[i][j] = fmaf(a[i], bfr[j], acc[i][j]);
        }
        __syncthreads();
    }

    // epilogue: +b1, exact gelu, store (vectorized)
#pragma unroll
    for (int i = 0; i < 8; i++) {
        int m  = ty*8 + i;
        int en = sEntry[m];
        if (en < 0) continue;
        float* Hrow = g_H + (size_t)en*Fm + col0 + tx*8;
        float v[8];
#pragma unroll
        for (int j = 0; j < 8; j++) {
            float t = acc[i][j] + b1[e*Fm + col0 + tx*8 + j];
            v[j] = 0.5f * t * (1.f + erff(t * 0.70710678118654752f));
        }
        *(float4*)&Hrow[0] = *(float4*)&v[0];
        *(float4*)&Hrow[4] = *(float4*)&v[4];
    }
}

// Y[entry] = H[entry] @ W2[e]^T + b2[e]
__global__ __launch_bounds__(256, 2)
void gemm2_kernel(const float* __restrict__ W2,
                  const float* __restrict__ b2) {
    int e    = blockIdx.z;
    int cnt  = g_count[e];
    int row0 = blockIdx.y * BM;
    if (row0 >= cnt) return;
    int col0 = blockIdx.x * BN;

    __shared__ float As[BK][BM + PAD];
    __shared__ float Bs[BK][BN + PAD];
    __shared__ int   sEntry[BM];

    int tid = threadIdx.x;
    if (tid < BM) {
        int i = row0 + tid;
        sEntry[tid] = (i < cnt) ? g_entries[e*Tm + i] : -1;
    }
    __syncthreads();

    float acc[8][8];
#pragma unroll
    for (int i = 0; i < 8; i++)
#pragma unroll
        for (int j = 0; j < 8; j++) acc[i][j] = 0.f;

    const float* Wb = W2 + (size_t)e*Dm*Fm + (size_t)col0*Fm;
    int tx = tid & 15, ty = tid >> 4;

    for (int k0 = 0; k0 < Fm; k0 += BK) {
#pragma unroll
        for (int j = 0; j < 8; j++) {
            int idx = tid + j*256;
            int k = idx & (BK-1);
            int m = idx >> 4;
            int en = sEntry[m];
            int r  = (en >= 0) ? en : 0;
            As[k][m] = g_H[(size_t)r*Fm + k0 + k];
        }
#pragma unroll
        for (int j = 0; j < 8; j++) {
            int idx = tid + j*256;
            int k = idx & (BK-1);
            int n = idx >> 4;
            Bs[k][n] = Wb[(size_t)n*Fm + k0 + k];
        }
        __syncthreads();
#pragma unroll
        for (int k = 0; k < BK; k++) {
            float a[8], bfr[8];
            *(float4*)&a[0]   = *(const float4*)&As[k][ty*8];
            *(float4*)&a[4]   = *(const float4*)&As[k][ty*8 + 4];
            *(float4*)&bfr[0] = *(const float4*)&Bs[k][tx*8];
            *(float4*)&bfr[4] = *(const float4*)&Bs[k][tx*8 + 4];
#pragma unroll
            for (int i = 0; i < 8; i++)
#pragma unroll
                for (int j = 0; j < 8; j++)
                    acc[i][j] = fmaf(a[i], bfr[j], acc[i][j]);
        }
        __syncthreads();
    }

#pragma unroll
    for (int i = 0; i < 8; i++) {
        int m  = ty*8 + i;
        int en = sEntry[m];
        if (en < 0) continue;
        float* Yrow = g_Y + (size_t)en*Dm + col0 + tx*8;
        float v[8];
#pragma unroll
        for (int j = 0; j < 8; j++)
            v[j] = acc[i][j] + b2[e*Dm + col0 + tx*8 + j];
        *(float4*)&Yrow[0] = *(float4*)&v[0];
        *(float4*)&Yrow[4] = *(float4*)&v[4];
    }
}

// out[t] = w0 * Y[t,slot0] + w1 * Y[t,slot1]
__global__ void combine_kernel(float* __restrict__ out) {
    int idx = blockIdx.x * blockDim.x + threadIdx.x;  // float4 index
    if (idx >= Tm*Dm/4) return;
    int t = idx / (Dm/4);
    int d4 = idx % (Dm/4);
    float w0 = g_topw[t*2 + 0];
    float w1 = g_topw[t*2 + 1];
    const float4 y0 = *(const float4*)&g_Y[(size_t)(t*2 + 0)*Dm + d4*4];
    const float4 y1 = *(const float4*)&g_Y[(size_t)(t*2 + 1)*Dm + d4*4];
    float4 o;
    o.x = w0*y0.x + w1*y1.x;
    o.y = w0*y0.y + w1*y1.y;
    o.z = w0*y0.z + w1*y1.z;
    o.w = w0*y0.w + w1*y1.w;
    *(float4*)&out[(size_t)idx*4] = o;
}

extern "C" void kernel_launch(void* const* d_in, const int* in_sizes, int n_in,
                              void* d_out, int out_size) {
    const float* x  = (const float*)d_in[0];
    const float* Wr = (const float*)d_in[1];
    const float* W1 = (const float*)d_in[2];
    const float* b1 = (const float*)d_in[3];
    const float* W2 = (const float*)d_in[4];
    const float* b2 = (const float*)d_in[5];
    float* out = (float*)d_out;

    zero_counts_kernel<<<1, 32>>>();
    router_kernel<<<(Tm*32 + 255)/256, 256>>>(x, Wr);

    dim3 g1(Fm/BN, (Tm + BM - 1)/BM, Em);   // (32, 32, 8)
    gemm1_kernel<<<g1, 256>>>(x, W1, b1);

    dim3 g2(Dm/BN, (Tm + BM - 1)/BM, Em);   // (8, 32, 8)
    gemm2_kernel<<<g2, 256>>>(W2, b2);

    combine_kernel<<<(Tm*Dm/4 + 255)/256, 256>>>(out);
}

// round 4
// speedup vs baseline: 2.6246x; 2.6246x over previous
#include <cuda_runtime.h>
#include <math.h>
#include <stdint.h>

#define Dm 1024
#define Fm 4096
#define Em 8
#define Tm 4096
#define TK (Tm*2)

// ---------------- scratch (static device globals) ----------------
__device__ int   g_count[Em];
__device__ int   g_entries[Em*Tm];      // entry = token*2 + slot
__device__ float g_topw[TK];
__device__ float g_H[(size_t)TK*Fm];    // 134 MB
__device__ float g_Y[(size_t)TK*Dm];    // 33.5 MB

// ---------------- PTX helpers (all plain-sm_103 ISA, no 'a' features) -----
__device__ __forceinline__ uint32_t s2u(const void* p) {
    uint32_t a;
    asm("{ .reg .u64 t; cvta.to.shared.u64 t, %1; cvt.u32.u64 %0, t; }" : "=r"(a) : "l"(p));
    return a;
}

__device__ __forceinline__ void cp16(uint32_t dst, const void* src) {
    asm volatile("cp.async.cg.shared.global [%0], [%1], 16;" :: "r"(dst), "l"(src));
}
#define CP_COMMIT() asm volatile("cp.async.commit_group;" ::: "memory")
#define CP_WAIT(n)  asm volatile("cp.async.wait_group %0;" :: "n"(n) : "memory")

__device__ __forceinline__ uint32_t f2tf(float f) {
    uint32_t u;
    asm("cvt.rna.tf32.f32 %0, %1;" : "=r"(u) : "f"(f));
    return u;
}

__device__ __forceinline__ void mma_tf32(float* d, const uint32_t* a, const uint32_t* b) {
    asm volatile(
        "mma.sync.aligned.m16n8k8.row.col.f32.tf32.tf32.f32 "
        "{%0,%1,%2,%3}, {%4,%5,%6,%7}, {%8,%9}, {%0,%1,%2,%3};"
        : "+f"(d[0]), "+f"(d[1]), "+f"(d[2]), "+f"(d[3])
        : "r"(a[0]), "r"(a[1]), "r"(a[2]), "r"(a[3]), "r"(b[0]), "r"(b[1]));
}

// ---------------- router ----------------
__global__ void zero_counts_kernel() {
    if (threadIdx.x < Em) g_count[threadIdx.x] = 0;
}

__global__ void router_kernel(const float* __restrict__ x,
                              const float* __restrict__ Wr) {
    int w    = (blockIdx.x * blockDim.x + threadIdx.x) >> 5;
    int lane = threadIdx.x & 31;
    if (w >= Tm) return;
    const float* xr = x + (size_t)w * Dm;
    float acc[Em];
#pragma unroll
    for (int e = 0; e < Em; e++) acc[e] = 0.f;
    for (int j = lane; j < Dm; j += 32) {
        float xv = xr[j];
#pragma unroll
        for (int e = 0; e < Em; e++) acc[e] = fmaf(xv, Wr[e*Dm + j], acc[e]);
    }
#pragma unroll
    for (int e = 0; e < Em; e++) {
#pragma unroll
        for (int off = 16; off; off >>= 1)
            acc[e] += __shfl_xor_sync(0xffffffffu, acc[e], off);
    }
    if (lane == 0) {
        int e0 = 0; float v0 = acc[0];
#pragma unroll
        for (int e = 1; e < Em; e++) if (acc[e] > v0) { v0 = acc[e]; e0 = e; }
        int e1 = -1; float v1 = -1e30f;
#pragma unroll
        for (int e = 0; e < Em; e++) if (e != e0 && acc[e] > v1) { v1 = acc[e]; e1 = e; }
        float b  = expf(v1 - v0);
        float w0 = 1.f / (1.f + b);
        float w1 = b  / (1.f + b);
        g_topw[w*2 + 0] = w0;
        g_topw[w*2 + 1] = w1;
        int p0 = atomicAdd(&g_count[e0], 1);
        g_entries[e0*Tm + p0] = w*2 + 0;
        int p1 = atomicAdd(&g_count[e1], 1);
        g_entries[e1*Tm + p1] = w*2 + 1;
    }
}

// ---------------- tf32 mma.sync gathered GEMM ----------------
// block tile 128(M gathered) x 128(N), K chunks of 32. 4 warps, warp tile 64x64.
// smem: per stage, A[128][36] + B[128][36] floats (pitch 36 -> conflict-free LDS).
#define PITCH 36
#define STG_HALF (128*PITCH*4)            // 18432 B
#define STG_BYTES (2*STG_HALF)            // 36864 B
#define NSTG 3
#define SMEM_DYN (NSTG*STG_BYTES)         // 110592 B

template<int KTOT, int ASTRIDE, int ASHIFT, int BSTRIDE, int NTOT, bool GELU>
__global__ __launch_bounds__(128, 2)
void moe_gemm(const float* __restrict__ Ain,
              const float* __restrict__ W,
              const float* __restrict__ bias)
{
    int e    = blockIdx.z;
    int cnt  = g_count[e];
    int row0 = blockIdx.y * 128;
    if (row0 >= cnt) return;
    int col0 = blockIdx.x * 128;

    extern __shared__ char dsm[];
    __shared__ int sEntry[128];

    int tid  = threadIdx.x;
    int lane = tid & 31;
    int w    = tid >> 5;

    const float* A = (ASHIFT == 1) ? Ain : (const float*)g_H;
    float* Out     = GELU ? g_H : g_Y;

    {
        int i = row0 + tid;
        sEntry[tid] = (i < cnt) ? g_entries[e*Tm + i] : -1;
    }
    __syncthreads();

    // per-thread copy row pointers (thread t owns row t of A tile and B tile)
    int enR = sEntry[tid];
    int rA  = (enR >= 0) ? (enR >> ASHIFT) : 0;
    const float* aSrc = A + (size_t)rA*ASTRIDE;
    const float* bSrc = W + (size_t)e*Fm*Dm + (size_t)(col0 + tid)*BSTRIDE;

    uint32_t sbase = s2u(dsm);
    constexpr int NCH = KTOT / 32;

    auto loadChunk = [&](int c) {
        int stg = c % NSTG;
        uint32_t aD = sbase + stg*STG_BYTES + tid*(PITCH*4);
        uint32_t bD = aD + STG_HALF;
        const float* as = aSrc + c*32;
        const float* bs = bSrc + c*32;
#pragma unroll
        for (int s = 0; s < 8; s++) cp16(aD + s*16, as + s*4);
#pragma unroll
        for (int s = 0; s < 8; s++) cp16(bD + s*16, bs + s*4);
        CP_COMMIT();
    };

    loadChunk(0); loadChunk(1); loadChunk(2);

    float acc[4][8][4];
#pragma unroll
    for (int i = 0; i < 4; i++)
#pragma unroll
        for (int j = 0; j < 8; j++)
#pragma unroll
            for (int q = 0; q < 4; q++) acc[i][j][q] = 0.f;

    int wm = w & 1, wn = w >> 1;    // warp tile: rows wm*64, cols wn*64
    int qr = lane >> 2;             // 0..7
    int qc = lane & 3;              // 0..3

    for (int c = 0; c < NCH; c++) {
        if (c < NCH-2)      CP_WAIT(2);
        else if (c == NCH-2) CP_WAIT(1);
        else                 CP_WAIT(0);
        __syncthreads();

        int stg = c % NSTG;
        const float* As = (const float*)(dsm + stg*STG_BYTES);
        const float* Bs = (const float*)(dsm + stg*STG_BYTES + STG_HALF);

#pragma unroll
        for (int ks = 0; ks < 4; ks++) {
            int kb = ks*8 + qc;
            uint32_t aF[4][4], bF[8][2];
#pragma unroll
            for (int mt = 0; mt < 4; mt++) {
                const float* p = As + (wm*64 + mt*16 + qr)*PITCH + kb;
                aF[mt][0] = f2tf(p[0]);
                aF[mt][1] = f2tf(p[8*PITCH]);
                aF[mt][2] = f2tf(p[4]);
                aF[mt][3] = f2tf(p[8*PITCH + 4]);
            }
#pragma unroll
            for (int nt = 0; nt < 8; nt++) {
                const float* p = Bs + (wn*64 + nt*8 + qr)*PITCH + kb;
                bF[nt][0] = f2tf(p[0]);
                bF[nt][1] = f2tf(p[4]);
            }
#pragma unroll
            for (int mt = 0; mt < 4; mt++)
#pragma unroll
                for (int nt = 0; nt < 8; nt++)
                    mma_tf32(acc[mt][nt], aF[mt], bF[nt]);
        }
        __syncthreads();
        if (c + 3 < NCH) loadChunk(c + 3);
    }

    // ---- epilogue: bias + (gelu) + scatter-store ----
    const float* bia = bias + e*NTOT + col0;
#pragma unroll
    for (int mt = 0; mt < 4; mt++) {
        int r0  = wm*64 + mt*16 + qr;
        int en0 = sEntry[r0];
        int en1 = sEntry[r0 + 8];
#pragma unroll
        for (int nt = 0; nt < 8; nt++) {
            int cc = wn*64 + nt*8 + 2*qc;
            float bv0 = bia[cc], bv1 = bia[cc + 1];
            if (en0 >= 0) {
                float t0 = acc[mt][nt][0] + bv0;
                float t1 = acc[mt][nt][1] + bv1;
                if (GELU) {
                    t0 = 0.5f*t0*(1.f + erff(t0*0.70710678118654752f));
                    t1 = 0.5f*t1*(1.f + erff(t1*0.70710678118654752f));
                }
                float2 v = make_float2(t0, t1);
                *(float2*)(Out + (size_t)en0*NTOT + col0 + cc) = v;
            }
            if (en1 >= 0) {
                float t0 = acc[mt][nt][2] + bv0;
                float t1 = acc[mt][nt][3] + bv1;
                if (GELU) {
                    t0 = 0.5f*t0*(1.f + erff(t0*0.70710678118654752f));
                    t1 = 0.5f*t1*(1.f + erff(t1*0.70710678118654752f));
                }
                float2 v = make_float2(t0, t1);
                *(float2*)(Out + (size_t)en1*NTOT + col0 + cc) = v;
            }
        }
    }
}

// ---------------- combine ----------------
__global__ void combine_kernel(float* __restrict__ out) {
    int idx = blockIdx.x * blockDim.x + threadIdx.x;  // float4 index
    if (idx >= Tm*Dm/4) return;
    int t  = idx / (Dm/4);
    int d4 = idx % (Dm/4);
    float w0 = g_topw[t*2 + 0];
    float w1 = g_topw[t*2 + 1];
    const float4 y0 = *(const float4*)&g_Y[(size_t)(t*2 + 0)*Dm + d4*4];
    const float4 y1 = *(const float4*)&g_Y[(size_t)(t*2 + 1)*Dm + d4*4];
    float4 o;
    o.x = w0*y0.x + w1*y1.x;
    o.y = w0*y0.y + w1*y1.y;
    o.z = w0*y0.z + w1*y1.z;
    o.w = w0*y0.w + w1*y1.w;
    *(float4*)&out[(size_t)idx*4] = o;
}

// ---------------- launch ----------------
extern "C" void kernel_launch(void* const* d_in, const int* in_sizes, int n_in,
                              void* d_out, int out_size) {
    const float* x  = (const float*)d_in[0];
    const float* Wr = (const float*)d_in[1];
    const float* W1 = (const float*)d_in[2];
    const float* b1 = (const float*)d_in[3];
    const float* W2 = (const float*)d_in[4];
    const float* b2 = (const float*)d_in[5];
    float* out = (float*)d_out;

    auto k1 = moe_gemm<Dm, Dm, 1, Dm, Fm, true>;    // H = gelu(x @ W1^T + b1)
    auto k2 = moe_gemm<Fm, Fm, 0, Fm, Dm, false>;   // Y = H @ W2^T + b2
    static bool attr_done = false;
    if (!attr_done) {
        cudaFuncSetAttribute(k1, cudaFuncAttributeMaxDynamicSharedMemorySize, SMEM_DYN);
        cudaFuncSetAttribute(k2, cudaFuncAttributeMaxDynamicSharedMemorySize, SMEM_DYN);
        attr_done = true;
    }

    zero_counts_kernel<<<1, 32>>>();
    router_kernel<<<(Tm*32 + 255)/256, 256>>>(x, Wr);

    dim3 g1(Fm/128, Tm/128, Em);   // (32, 32, 8), early-exit on empty row tiles
    k1<<<g1, 128, SMEM_DYN>>>(x, W1, b1);

    dim3 g2(Dm/128, Tm/128, Em);   // (8, 32, 8)
    k2<<<g2, 128, SMEM_DYN>>>(nullptr, W2, b2);

    combine_kernel<<<(Tm*Dm/4 + 255)/256, 256>>>(out);
}

// round 5
// speedup vs baseline: 3.2467x; 1.2370x over previous
#include <cuda_runtime.h>
#include <math.h>
#include <stdint.h>

#define Dm 1024
#define Fm 4096
#define Em 8
#define Tm 4096
#define TK (Tm*2)

// ---------------- scratch (static device globals) ----------------
__device__ int   g_count[Em];
__device__ int   g_entries[Em*Tm];      // entry = token*2 + slot
__device__ float g_topw[TK];
__device__ float g_Xr[(size_t)Tm*Dm];   // tf32-pre-rounded x, 16 MB
__device__ float g_H[(size_t)TK*Fm];    // 134 MB (stored tf32-pre-rounded)
__device__ float g_Y[(size_t)TK*Dm];    // 33.5 MB (full fp32)

// ---------------- PTX helpers (plain-sm_103 ISA) ----------------
__device__ __forceinline__ uint32_t s2u(const void* p) {
    uint32_t a;
    asm("{ .reg .u64 t; cvta.to.shared.u64 t, %1; cvt.u32.u64 %0, t; }" : "=r"(a) : "l"(p));
    return a;
}

__device__ __forceinline__ void cp16(uint32_t dst, const void* src) {
    asm volatile("cp.async.cg.shared.global [%0], [%1], 16;" :: "r"(dst), "l"(src));
}
#define CP_COMMIT() asm volatile("cp.async.commit_group;" ::: "memory")
#define CP_WAIT(n)  asm volatile("cp.async.wait_group %0;" :: "n"(n) : "memory")

__device__ __forceinline__ uint32_t f2tf(float f) {
    uint32_t u;
    asm("cvt.rna.tf32.f32 %0, %1;" : "=r"(u) : "f"(f));
    return u;
}

__device__ __forceinline__ void mma_tf32(float* d, const uint32_t* a, const uint32_t* b) {
    asm volatile(
        "mma.sync.aligned.m16n8k8.row.col.f32.tf32.tf32.f32 "
        "{%0,%1,%2,%3}, {%4,%5,%6,%7}, {%8,%9}, {%0,%1,%2,%3};"
        : "+f"(d[0]), "+f"(d[1]), "+f"(d[2]), "+f"(d[3])
        : "r"(a[0]), "r"(a[1]), "r"(a[2]), "r"(a[3]), "r"(b[0]), "r"(b[1]));
}

// ---------------- router (also writes tf32-rounded x copy) ----------------
__global__ void zero_counts_kernel() {
    if (threadIdx.x < Em) g_count[threadIdx.x] = 0;
}

__global__ void router_kernel(const float* __restrict__ x,
                              const float* __restrict__ Wr) {
    int w    = (blockIdx.x * blockDim.x + threadIdx.x) >> 5;
    int lane = threadIdx.x & 31;
    if (w >= Tm) return;
    const float* xr = x + (size_t)w * Dm;
    float* xo = g_Xr + (size_t)w * Dm;
    float acc[Em];
#pragma unroll
    for (int e = 0; e < Em; e++) acc[e] = 0.f;
    for (int j = lane; j < Dm; j += 32) {
        float xv = xr[j];
        xo[j] = __uint_as_float(f2tf(xv));   // pre-rounded copy for the MMA A-path
#pragma unroll
        for (int e = 0; e < Em; e++) acc[e] = fmaf(xv, Wr[e*Dm + j], acc[e]);
    }
#pragma unroll
    for (int e = 0; e < Em; e++) {
#pragma unroll
        for (int off = 16; off; off >>= 1)
            acc[e] += __shfl_xor_sync(0xffffffffu, acc[e], off);
    }
    if (lane == 0) {
        int e0 = 0; float v0 = acc[0];
#pragma unroll
        for (int e = 1; e < Em; e++) if (acc[e] > v0) { v0 = acc[e]; e0 = e; }
        int e1 = -1; float v1 = -1e30f;
#pragma unroll
        for (int e = 0; e < Em; e++) if (e != e0 && acc[e] > v1) { v1 = acc[e]; e1 = e; }
        float b  = expf(v1 - v0);
        float w0 = 1.f / (1.f + b);
        float w1 = b  / (1.f + b);
        g_topw[w*2 + 0] = w0;
        g_topw[w*2 + 1] = w1;
        int p0 = atomicAdd(&g_count[e0], 1);
        g_entries[e0*Tm + p0] = w*2 + 0;
        int p1 = atomicAdd(&g_count[e1], 1);
        g_entries[e1*Tm + p1] = w*2 + 1;
    }
}

// ---------------- tf32 mma.sync gathered GEMM ----------------
// block tile 128(M gathered) x 128(N), K chunks of 32. 8 warps, warp tile 64x32.
// smem pitch 40 floats -> conflict-free LDS.64 fragment loads (k-pair trick).
#define PITCH 40
#define STG_HALF (128*PITCH*4)            // 20480 B
#define STG_BYTES (2*STG_HALF)            // 40960 B
#define SMEM_DYN (2*STG_BYTES)            // 81920 B (2 stages)

template<int KTOT, int ASTRIDE, int ASHIFT, int BSTRIDE, int NTOT, bool GELU>
__global__ __launch_bounds__(256, 2)
void moe_gemm(const float* __restrict__ W,
              const float* __restrict__ bias)
{
    int e    = blockIdx.z;
    int cnt  = g_count[e];
    int row0 = blockIdx.y * 128;
    if (row0 >= cnt) return;
    int col0 = blockIdx.x * 128;

    extern __shared__ char dsm[];
    __shared__ int sEntry[128];

    int tid  = threadIdx.x;
    int lane = tid & 31;
    int w    = tid >> 5;

    const float* A = (ASHIFT == 1) ? (const float*)g_Xr : (const float*)g_H;
    float* Out     = GELU ? g_H : g_Y;

    if (tid < 128) {
        int i = row0 + tid;
        sEntry[tid] = (i < cnt) ? g_entries[e*Tm + i] : -1;
    }
    __syncthreads();

    // copy assignment: thread t owns half-row (t&1) of tile-row (t>>1)
    int rowC = tid >> 1, segC = tid & 1;
    int enR  = sEntry[rowC];
    int rA   = (enR >= 0) ? (enR >> ASHIFT) : 0;
    const float* aSrc = A + (size_t)rA*ASTRIDE + segC*16;
    const float* bSrc = W + (size_t)e*Fm*Dm + (size_t)(col0 + rowC)*BSTRIDE + segC*16;

    uint32_t sbase = s2u(dsm);
    uint32_t cpA = sbase + rowC*(PITCH*4) + segC*64;
    uint32_t cpB = cpA + STG_HALF;
    constexpr int NCH = KTOT / 32;

    auto loadChunk = [&](int c) {
        int stg = c & 1;
        uint32_t aD = cpA + stg*STG_BYTES;
        uint32_t bD = cpB + stg*STG_BYTES;
        const float* as = aSrc + c*32;
        const float* bs = bSrc + c*32;
#pragma unroll
        for (int s = 0; s < 4; s++) cp16(aD + s*16, as + s*4);
#pragma unroll
        for (int s = 0; s < 4; s++) cp16(bD + s*16, bs + s*4);
        CP_COMMIT();
    };

    loadChunk(0); loadChunk(1);

    float acc[4][4][4];
#pragma unroll
    for (int i = 0; i < 4; i++)
#pragma unroll
        for (int j = 0; j < 4; j++)
#pragma unroll
            for (int q = 0; q < 4; q++) acc[i][j][q] = 0.f;

    int wm = w & 1, wn = w >> 1;    // warp tile: rows wm*64..+63, cols wn*32..+31
    int qr = lane >> 2;             // 0..7
    int qc = lane & 3;              // 0..3

    for (int c = 0; c < NCH; c++) {
        if (c + 1 < NCH) CP_WAIT(1); else CP_WAIT(0);
        __syncthreads();

        int stg = c & 1;
        const float* As = (const float*)(dsm + stg*STG_BYTES);
        const float* Bs = (const float*)(dsm + stg*STG_BYTES + STG_HALF);

#pragma unroll
        for (int ks = 0; ks < 4; ks++) {
            // k-slot permutation: mma slots (qc, qc+4) carry physical k (2qc, 2qc+1)
            int kb = ks*8 + 2*qc;
            uint32_t aF[4][4], bF[4][2];
#pragma unroll
            for (int mt = 0; mt < 4; mt++) {
                int r = wm*64 + mt*16 + qr;
                float2 lo = *(const float2*)(As + r*PITCH + kb);
                float2 hi = *(const float2*)(As + (r+8)*PITCH + kb);
                aF[mt][0] = __float_as_uint(lo.x);   // pre-rounded: no cvt
                aF[mt][2] = __float_as_uint(lo.y);
                aF[mt][1] = __float_as_uint(hi.x);
                aF[mt][3] = __float_as_uint(hi.y);
            }
#pragma unroll
            for (int nt = 0; nt < 4; nt++) {
                int n = wn*32 + nt*8 + qr;
                float2 bv = *(const float2*)(Bs + n*PITCH + kb);
                bF[nt][0] = f2tf(bv.x);
                bF[nt][1] = f2tf(bv.y);
            }
#pragma unroll
            for (int mt = 0; mt < 4; mt++)
#pragma unroll
                for (int nt = 0; nt < 4; nt++)
                    mma_tf32(acc[mt][nt], aF[mt], bF[nt]);
        }
        __syncthreads();
        if (c + 2 < NCH) loadChunk(c + 2);
    }

    // ---- epilogue: bias + (gelu, tf32-round) + scatter-store ----
    const float* bia = bias + e*NTOT + col0;
#pragma unroll
    for (int mt = 0; mt < 4; mt++) {
        int r0  = wm*64 + mt*16 + qr;
        int en0 = sEntry[r0];
        int en1 = sEntry[r0 + 8];
#pragma unroll
        for (int nt = 0; nt < 4; nt++) {
            int cc = wn*32 + nt*8 + 2*qc;
            float bv0 = bia[cc], bv1 = bia[cc + 1];
            if (en0 >= 0) {
                float t0 = acc[mt][nt][0] + bv0;
                float t1 = acc[mt][nt][1] + bv1;
                if (GELU) {
                    t0 = 0.5f*t0*(1.f + erff(t0*0.70710678118654752f));
                    t1 = 0.5f*t1*(1.f + erff(t1*0.70710678118654752f));
                    t0 = __uint_as_float(f2tf(t0));   // store H pre-rounded
                    t1 = __uint_as_float(f2tf(t1));
                }
                *(float2*)(Out + (size_t)en0*NTOT + col0 + cc) = make_float2(t0, t1);
            }
            if (en1 >= 0) {
                float t0 = acc[mt][nt][2] + bv0;
                float t1 = acc[mt][nt][3] + bv1;
                if (GELU) {
                    t0 = 0.5f*t0*(1.f + erff(t0*0.70710678118654752f));
                    t1 = 0.5f*t1*(1.f + erff(t1*0.70710678118654752f));
                    t0 = __uint_as_float(f2tf(t0));
                    t1 = __uint_as_float(f2tf(t1));
                }
                *(float2*)(Out + (size_t)en1*NTOT + col0 + cc) = make_float2(t0, t1);
            }
        }
    }
}

// ---------------- combine ----------------
__global__ void combine_kernel(float* __restrict__ out) {
    int idx = blockIdx.x * blockDim.x + threadIdx.x;  // float4 index
    if (idx >= Tm*Dm/4) return;
    int t  = idx / (Dm/4);
    int d4 = idx % (Dm/4);
    float w0 = g_topw[t*2 + 0];
    float w1 = g_topw[t*2 + 1];
    const float4 y0 = *(const float4*)&g_Y[(size_t)(t*2 + 0)*Dm + d4*4];
    const float4 y1 = *(const float4*)&g_Y[(size_t)(t*2 + 1)*Dm + d4*4];
    float4 o;
    o.x = w0*y0.x + w1*y1.x;
    o.y = w0*y0.y + w1*y1.y;
    o.z = w0*y0.z + w1*y1.z;
    o.w = w0*y0.w + w1*y1.w;
    *(float4*)&out[(size_t)idx*4] = o;
}

// ---------------- launch ----------------
extern "C" void kernel_launch(void* const* d_in, const int* in_sizes, int n_in,
                              void* d_out, int out_size) {
    const float* x  = (const float*)d_in[0];
    const float* Wr = (const float*)d_in[1];
    const float* W1 = (const float*)d_in[2];
    const float* b1 = (const float*)d_in[3];
    const float* W2 = (const float*)d_in[4];
    const float* b2 = (const float*)d_in[5];
    float* out = (float*)d_out;

    auto k1 = moe_gemm<Dm, Dm, 1, Dm, Fm, true>;    // H = gelu(Xr @ W1^T + b1)
    auto k2 = moe_gemm<Fm, Fm, 0, Fm, Dm, false>;   // Y = H @ W2^T + b2
    static bool attr_done = false;
    if (!attr_done) {
        cudaFuncSetAttribute(k1, cudaFuncAttributeMaxDynamicSharedMemorySize, SMEM_DYN);
        cudaFuncSetAttribute(k2, cudaFuncAttributeMaxDynamicSharedMemorySize, SMEM_DYN);
        attr_done = true;
    }

    zero_counts_kernel<<<1, 32>>>();
    router_kernel<<<(Tm*32 + 255)/256, 256>>>(x, Wr);

    dim3 g1(Fm/128, Tm/128, Em);   // (32, 32, 8)
    k1<<<g1, 256, SMEM_DYN>>>(W1, b1);

    dim3 g2(Dm/128, Tm/128, Em);   // (8, 32, 8)
    k2<<<g2, 256, SMEM_DYN>>>(W2, b2);

    combine_kernel<<<(Tm*Dm/4 + 255)/256, 256>>>(out);
}